// round 3
// baseline (speedup 1.0000x reference)
#include <cuda_runtime.h>
#include <math.h>

#define T_DIM 2048
#define B_DIM 4
#define D_DIM 1024

// Scratch (device globals -- no allocation allowed in kernel_launch)
__device__ float g_kv[(size_t)T_DIM * B_DIM * 2 * D_DIM];   // [t*B+b][2D]  (K | V)
__device__ float g_ctx[(size_t)T_DIM * B_DIM * D_DIM];      // [t][b][d]

// ---------------------------------------------------------------------------
// Tiled SGEMM: C[m][n] = alpha * sum_k A[m][k] * B(k,n)  (+ bias[n])
//   A is row-major with row stride lda (K contiguous).
//   If B_KMAJOR: B is [n][k] row-major, row stride ldb (NT gemm).
//   Else:        B is [k][n] row-major, row stride ldb (NN gemm).
// Batched via blockIdx.z with element strides sAz/sBz/sCz.
// All of M, N multiples of 64; K multiple of 16; pointers 16B aligned.
// ---------------------------------------------------------------------------
template <bool B_KMAJOR>
__global__ __launch_bounds__(256) void sgemm_kernel(
    const float* __restrict__ A, int lda, long sAz,
    const float* __restrict__ Bp, int ldb, long sBz,
    float* __restrict__ C, int ldc, long sCz,
    const float* __restrict__ bias,
    float alpha, int M, int N, int K)
{
    __shared__ float As[16][68];   // [k][m], pad 4 keeps 16B alignment
    __shared__ float Bs[16][68];   // [k][n]

    const int tid = threadIdx.x;
    const int tx = tid & 15;       // -> n
    const int ty = tid >> 4;       // -> m
    const int m0 = blockIdx.y * 64;
    const int n0 = blockIdx.x * 64;

    A  += (long)blockIdx.z * sAz;
    Bp += (long)blockIdx.z * sBz;
    C  += (long)blockIdx.z * sCz;

    // loader indices (K-major tiles): 256 threads x float4 = 1024 floats
    const int la_m = tid >> 2;          // 0..63
    const int la_k = (tid & 3) * 4;     // 0,4,8,12
    // loader indices (N-major B tile)
    const int lb_k = tid >> 4;          // 0..15
    const int lb_n = (tid & 15) * 4;    // 0..60

    float acc[4][4] = {};

    for (int k0 = 0; k0 < K; k0 += 16) {
        {
            const float4 v = *(const float4*)&A[(long)(m0 + la_m) * lda + k0 + la_k];
            As[la_k + 0][la_m] = v.x;
            As[la_k + 1][la_m] = v.y;
            As[la_k + 2][la_m] = v.z;
            As[la_k + 3][la_m] = v.w;
        }
        if (B_KMAJOR) {
            const float4 v = *(const float4*)&Bp[(long)(n0 + la_m) * ldb + k0 + la_k];
            Bs[la_k + 0][la_m] = v.x;
            Bs[la_k + 1][la_m] = v.y;
            Bs[la_k + 2][la_m] = v.z;
            Bs[la_k + 3][la_m] = v.w;
        } else {
            const float4 v = *(const float4*)&Bp[(long)(k0 + lb_k) * ldb + n0 + lb_n];
            Bs[lb_k][lb_n + 0] = v.x;
            Bs[lb_k][lb_n + 1] = v.y;
            Bs[lb_k][lb_n + 2] = v.z;
            Bs[lb_k][lb_n + 3] = v.w;
        }
        __syncthreads();

        #pragma unroll
        for (int k = 0; k < 16; k++) {
            float a[4], b[4];
            #pragma unroll
            for (int i = 0; i < 4; i++) a[i] = As[k][ty * 4 + i];
            #pragma unroll
            for (int j = 0; j < 4; j++) b[j] = Bs[k][tx * 4 + j];
            #pragma unroll
            for (int i = 0; i < 4; i++)
                #pragma unroll
                for (int j = 0; j < 4; j++)
                    acc[i][j] += a[i] * b[j];
        }
        __syncthreads();
    }

    #pragma unroll
    for (int i = 0; i < 4; i++) {
        const int m = m0 + ty * 4 + i;
        #pragma unroll
        for (int j = 0; j < 4; j++) {
            const int n = n0 + tx * 4 + j;
            float v = alpha * acc[i][j];
            if (bias) v += bias[n];
            C[(long)m * ldc + n] = v;
        }
    }
}

// ---------------------------------------------------------------------------
// In-place row softmax: one block per row of length S (=2048), 256 threads.
// ---------------------------------------------------------------------------
__global__ __launch_bounds__(256) void softmax_kernel(float* __restrict__ P, int S)
{
    float* row = P + (long)blockIdx.x * S;
    const int tid = threadIdx.x;

    float vals[8];
    float mx = -INFINITY;
    #pragma unroll
    for (int i = 0; i < 8; i++) {
        vals[i] = row[tid + i * 256];
        mx = fmaxf(mx, vals[i]);
    }

    __shared__ float red[256];
    red[tid] = mx;
    __syncthreads();
    for (int s = 128; s > 0; s >>= 1) {
        if (tid < s) red[tid] = fmaxf(red[tid], red[tid + s]);
        __syncthreads();
    }
    mx = red[0];
    __syncthreads();

    float sum = 0.f;
    #pragma unroll
    for (int i = 0; i < 8; i++) {
        vals[i] = __expf(vals[i] - mx);
        sum += vals[i];
    }
    red[tid] = sum;
    __syncthreads();
    for (int s = 128; s > 0; s >>= 1) {
        if (tid < s) red[tid] += red[tid + s];
        __syncthreads();
    }
    const float inv = 1.0f / red[0];

    #pragma unroll
    for (int i = 0; i < 8; i++) row[tid + i * 256] = vals[i] * inv;
}

// ---------------------------------------------------------------------------
extern "C" void kernel_launch(void* const* d_in, const int* in_sizes, int n_in,
                              void* d_out, int out_size)
{
    const float* query = (const float*)d_in[0];   // [T][B][D]
    const float* input_feature = (const float*)d_in[1];   // [T][B][D]
    const float* Wi = (const float*)d_in[2];   // [2D][D]
    const float* bi = (const float*)d_in[3];   // [2D]
    const float* Wo = (const float*)d_in[4];   // [D][D]
    const float* bo = (const float*)d_in[5];   // [D]

    float* out = (float*)d_out;
    float* attn_out = out;                                    // [T][B][D]
    float* aw = out + (size_t)T_DIM * B_DIM * D_DIM;          // [B][T][T]

    float* kv = nullptr;
    float* ctx = nullptr;
    cudaGetSymbolAddress((void**)&kv, g_kv);
    cudaGetSymbolAddress((void**)&ctx, g_ctx);

    const dim3 blk(256);
    const float scale = 1.0f / sqrtf((float)D_DIM);   // 0.03125

    // 1) KV projection: kv[tb][e] = input_feature[tb][:] . Wi[e][:] + bi[e]
    //    M=8192, N=2048, K=1024   (NT)
    sgemm_kernel<true><<<dim3(2 * D_DIM / 64, T_DIM * B_DIM / 64, 1), blk>>>(
        input_feature, D_DIM, 0,
        Wi, D_DIM, 0,
        kv, 2 * D_DIM, 0,
        bi, 1.0f, T_DIM * B_DIM, 2 * D_DIM, D_DIM);

    // 2) Scores: aw[b][t][s] = scale * q[t][b][:] . k[s][b][:]
    //    A = query + b*D (row stride B*D);  B = kv + b*2D (row stride B*2D), K-major
    sgemm_kernel<true><<<dim3(T_DIM / 64, T_DIM / 64, B_DIM), blk>>>(
        query, B_DIM * D_DIM, (long)D_DIM,
        kv, B_DIM * 2 * D_DIM, (long)(2 * D_DIM),
        aw, T_DIM, (long)T_DIM * T_DIM,
        nullptr, scale, T_DIM, T_DIM, D_DIM);

    // 3) Softmax over s, in place in the attn_weights output slice
    softmax_kernel<<<B_DIM * T_DIM, 256>>>(aw, T_DIM);

    // 4) Context: ctx[t][b][d] = sum_s aw[b][t][s] * v[s][b][d]
    //    B = kv + b*2D + D, rows s (stride B*2D), N-major over d  (NN)
    //    K = T_DIM (contraction over s) -- this was the R1 bug (was D_DIM).
    sgemm_kernel<false><<<dim3(D_DIM / 64, T_DIM / 64, B_DIM), blk>>>(
        aw, T_DIM, (long)T_DIM * T_DIM,
        kv + D_DIM, B_DIM * 2 * D_DIM, (long)(2 * D_DIM),
        ctx, B_DIM * D_DIM, (long)D_DIM,
        nullptr, 1.0f, T_DIM, D_DIM, T_DIM);

    // 5) Out projection: attn_out[tb][e] = ctx[tb][:] . Wo[e][:] + bo[e]
    sgemm_kernel<true><<<dim3(D_DIM / 64, T_DIM * B_DIM / 64, 1), blk>>>(
        ctx, D_DIM, 0,
        Wo, D_DIM, 0,
        attn_out, D_DIM, 0,
        bo, 1.0f, T_DIM * B_DIM, D_DIM, D_DIM);
}

// round 5
// speedup vs baseline: 2.1970x; 2.1970x over previous
#include <cuda_runtime.h>
#include <cuda_bf16.h>
#include <math.h>
#include <stdint.h>

#define T_DIM 2048
#define B_DIM 4
#define D_DIM 1024
#define KEXT1 (3 * D_DIM)     // 3072
#define KEXT2 (3 * T_DIM)     // 6144

// ---------------------------------------------------------------------------
// Device scratch
// ---------------------------------------------------------------------------
__device__ float         g_kv  [(size_t)T_DIM * B_DIM * 2 * D_DIM];
__device__ float         g_ctx [(size_t)T_DIM * B_DIM * D_DIM];
__device__ __nv_bfloat16 g_feat_ext[(size_t)T_DIM * B_DIM * KEXT1];
__device__ __nv_bfloat16 g_wi_ext  [(size_t)2 * D_DIM * KEXT1];
__device__ __nv_bfloat16 g_wo_ext  [(size_t)D_DIM * KEXT1];
__device__ __nv_bfloat16 g_q_ext   [(size_t)B_DIM * T_DIM * KEXT1];
__device__ __nv_bfloat16 g_k_ext   [(size_t)B_DIM * T_DIM * KEXT1];
__device__ __nv_bfloat16 g_p_ext   [(size_t)B_DIM * T_DIM * KEXT2];
__device__ __nv_bfloat16 g_vt_ext  [(size_t)B_DIM * D_DIM * KEXT2];
__device__ __nv_bfloat16 g_ctx_ext [(size_t)T_DIM * B_DIM * KEXT1];

__device__ __forceinline__ uint32_t smem_u32(const void* p) {
    uint32_t a;
    asm("{ .reg .u64 t; cvta.to.shared.u64 t, %1; cvt.u32.u64 %0, t; }" : "=r"(a) : "l"(p));
    return a;
}

// ---------------------------------------------------------------------------
// bf16 NT GEMM via mma.sync (sm_80-feature-set; works on plain sm_103 PTX)
//   C[m][n] = sum_k A[m][k]*B[n][k] (+ bias[n])
// Block 128x128x32, 256 threads, warp grid 2(m) x 4(n), warp tile 64x32.
// ---------------------------------------------------------------------------
#define BM 128
#define BN 128
#define BK 32
#define PITCH 40   // bf16 elements per SMEM row (64B data + 16B pad)

__global__ __launch_bounds__(256) void gemm_mma(
    const __nv_bfloat16* __restrict__ A, long sAz, int lda,
    const __nv_bfloat16* __restrict__ B, long sBz, int ldb,
    float* __restrict__ C, long sCz, int ldc,
    const float* __restrict__ bias, int Kext)
{
    __shared__ __nv_bfloat16 As[2][BM][PITCH];
    __shared__ __nv_bfloat16 Bs[2][BN][PITCH];

    const int tid  = threadIdx.x;
    const int wid  = tid >> 5;
    const int lane = tid & 31;
    const int wm = (wid >> 2) * 64;   // warp m offset in tile
    const int wn = (wid & 3) * 32;    // warp n offset in tile
    const int m0 = blockIdx.y * BM;
    const int n0 = blockIdx.x * BN;

    A += (long)blockIdx.z * sAz;
    B += (long)blockIdx.z * sBz;
    C += (long)blockIdx.z * sCz;

    const uint32_t sA = smem_u32(As);
    const uint32_t sB = smem_u32(Bs);
    const uint32_t BUFA = (uint32_t)(BM * PITCH * 2);   // bytes per A buffer
    const uint32_t BUFB = (uint32_t)(BN * PITCH * 2);

    // cp.async fill: 512 chunks of 16B per tile, 2 per thread
    const int ld_row = tid >> 2;        // 0..63  (x2 => 128 rows)
    const int ld_c   = (tid & 3) * 16;  // byte col 0,16,32,48

    auto load_tiles = [&](int buf, int k0) {
        #pragma unroll
        for (int h = 0; h < 2; h++) {
            const int row = ld_row + h * 64;
            const uint32_t da = sA + buf * BUFA + row * (PITCH * 2) + ld_c;
            const __nv_bfloat16* ga = A + (size_t)(m0 + row) * lda + k0 + (ld_c >> 1);
            asm volatile("cp.async.cg.shared.global [%0], [%1], 16;" :: "r"(da), "l"(ga));
            const uint32_t db = sB + buf * BUFB + row * (PITCH * 2) + ld_c;
            const __nv_bfloat16* gb = B + (size_t)(n0 + row) * ldb + k0 + (ld_c >> 1);
            asm volatile("cp.async.cg.shared.global [%0], [%1], 16;" :: "r"(db), "l"(gb));
        }
        asm volatile("cp.async.commit_group;" ::: "memory");
    };

    float acc[4][4][4];
    #pragma unroll
    for (int i = 0; i < 4; i++)
        #pragma unroll
        for (int j = 0; j < 4; j++)
            #pragma unroll
            for (int r = 0; r < 4; r++) acc[i][j][r] = 0.f;

    const int niter = Kext / BK;
    load_tiles(0, 0);
    int buf = 0;

    for (int kt = 0; kt < niter; kt++) {
        if (kt + 1 < niter) {
            load_tiles(buf ^ 1, (kt + 1) * BK);
            asm volatile("cp.async.wait_group 1;" ::: "memory");
        } else {
            asm volatile("cp.async.wait_group 0;" ::: "memory");
        }
        __syncthreads();

        #pragma unroll
        for (int k16 = 0; k16 < 2; k16++) {
            // A fragments: 4 m-tiles
            uint32_t af[4][4];
            #pragma unroll
            for (int mt = 0; mt < 4; mt++) {
                const int row = wm + mt * 16 + (lane & 15);
                const int col = (lane >> 4) * 8 + k16 * 16;
                const uint32_t addr = sA + buf * BUFA + row * (PITCH * 2) + col * 2;
                asm volatile("ldmatrix.sync.aligned.m8n8.x4.shared.b16 {%0,%1,%2,%3}, [%4];"
                             : "=r"(af[mt][0]), "=r"(af[mt][1]), "=r"(af[mt][2]), "=r"(af[mt][3])
                             : "r"(addr));
            }
            // B fragments: 4 n-tiles (2 ldmatrix.x4, each covers 2 n-tiles)
            uint32_t bf[4][2];
            #pragma unroll
            for (int pr = 0; pr < 2; pr++) {
                const int row = wn + pr * 16 + ((lane >> 4) & 1) * 8 + (lane & 7);
                const int col = ((lane >> 3) & 1) * 8 + k16 * 16;
                const uint32_t addr = sB + buf * BUFB + row * (PITCH * 2) + col * 2;
                asm volatile("ldmatrix.sync.aligned.m8n8.x4.shared.b16 {%0,%1,%2,%3}, [%4];"
                             : "=r"(bf[pr * 2][0]), "=r"(bf[pr * 2][1]),
                               "=r"(bf[pr * 2 + 1][0]), "=r"(bf[pr * 2 + 1][1])
                             : "r"(addr));
            }
            #pragma unroll
            for (int mt = 0; mt < 4; mt++)
                #pragma unroll
                for (int nt = 0; nt < 4; nt++) {
                    asm volatile(
                        "mma.sync.aligned.m16n8k16.row.col.f32.bf16.bf16.f32 "
                        "{%0,%1,%2,%3}, {%4,%5,%6,%7}, {%8,%9}, {%0,%1,%2,%3};"
                        : "+f"(acc[mt][nt][0]), "+f"(acc[mt][nt][1]),
                          "+f"(acc[mt][nt][2]), "+f"(acc[mt][nt][3])
                        : "r"(af[mt][0]), "r"(af[mt][1]), "r"(af[mt][2]), "r"(af[mt][3]),
                          "r"(bf[nt][0]), "r"(bf[nt][1]));
                }
        }
        __syncthreads();
        buf ^= 1;
    }

    // Epilogue. c0,c1: row g, cols 2t,2t+1 ; c2,c3: row g+8.
    const int g  = lane >> 2;
    const int tg = lane & 3;
    #pragma unroll
    for (int mt = 0; mt < 4; mt++) {
        const int mrow0 = m0 + wm + mt * 16 + g;
        #pragma unroll
        for (int nt = 0; nt < 4; nt++) {
            const int n = n0 + wn + nt * 8 + 2 * tg;
            float b0 = 0.f, b1 = 0.f;
            if (bias) { b0 = bias[n]; b1 = bias[n + 1]; }
            float2 v0 = make_float2(acc[mt][nt][0] + b0, acc[mt][nt][1] + b1);
            float2 v1 = make_float2(acc[mt][nt][2] + b0, acc[mt][nt][3] + b1);
            *(float2*)(C + (size_t)mrow0 * ldc + n) = v0;
            *(float2*)(C + (size_t)(mrow0 + 8) * ldc + n) = v1;
        }
    }
}

// ---------------------------------------------------------------------------
// fp32 -> bf16 hi/lo split, 3-segment K layout.  modeA: [hi|hi|lo], else [hi|lo|hi]
// ---------------------------------------------------------------------------
__global__ __launch_bounds__(256) void split_conv(
    const float* __restrict__ src, long sb, long srs,
    __nv_bfloat16* __restrict__ dst, int rows, int K, float scale, int modeA)
{
    const long idx = (long)blockIdx.x * 256 + threadIdx.x;
    const int r = (int)(idx / K);
    const int k = (int)(idx % K);
    if (r >= rows) return;
    const float x = src[(long)blockIdx.z * sb + (long)r * srs + k] * scale;
    const __nv_bfloat16 hi = __float2bfloat16_rn(x);
    const __nv_bfloat16 lo = __float2bfloat16_rn(x - __bfloat162float(hi));
    __nv_bfloat16* d = dst + (size_t)blockIdx.z * rows * 3 * K + (size_t)r * 3 * K + k;
    d[0] = hi;
    d[K] = modeA ? hi : lo;
    d[2 * K] = modeA ? lo : hi;
}

// ---------------------------------------------------------------------------
// V transpose + B-mode split: kv V part [s][b][d] -> vt[b][d][hi(s)|lo(s)|hi(s)]
// ---------------------------------------------------------------------------
__global__ __launch_bounds__(256) void vt_conv(
    const float* __restrict__ kv, __nv_bfloat16* __restrict__ vt)
{
    __shared__ float tile[32][33];
    const int b = blockIdx.z;
    const int s0 = blockIdx.x * 32;
    const int d0 = blockIdx.y * 32;
    const int tx = threadIdx.x & 31;
    const int ty = threadIdx.x >> 5;

    #pragma unroll
    for (int r = 0; r < 4; r++) {
        const int s = s0 + ty + r * 8;
        tile[ty + r * 8][tx] = kv[(size_t)s * (B_DIM * 2 * D_DIM) + b * (2 * D_DIM) + D_DIM + d0 + tx];
    }
    __syncthreads();
    #pragma unroll
    for (int r = 0; r < 4; r++) {
        const int d = d0 + ty + r * 8;
        const int s = s0 + tx;
        const float x = tile[tx][ty + r * 8];
        const __nv_bfloat16 hi = __float2bfloat16_rn(x);
        const __nv_bfloat16 lo = __float2bfloat16_rn(x - __bfloat162float(hi));
        __nv_bfloat16* dst = vt + (size_t)b * D_DIM * KEXT2 + (size_t)d * KEXT2 + s;
        dst[0] = hi;
        dst[T_DIM] = lo;
        dst[2 * T_DIM] = hi;
    }
}

// ---------------------------------------------------------------------------
__global__ __launch_bounds__(256) void softmax_kernel(float* __restrict__ P)
{
    float* row = P + (long)blockIdx.x * T_DIM;
    const int tid = threadIdx.x;
    float vals[8];
    float mx = -INFINITY;
    #pragma unroll
    for (int i = 0; i < 8; i++) { vals[i] = row[tid + i * 256]; mx = fmaxf(mx, vals[i]); }

    __shared__ float red[256];
    red[tid] = mx; __syncthreads();
    for (int s = 128; s > 0; s >>= 1) { if (tid < s) red[tid] = fmaxf(red[tid], red[tid + s]); __syncthreads(); }
    mx = red[0]; __syncthreads();

    float sum = 0.f;
    #pragma unroll
    for (int i = 0; i < 8; i++) { vals[i] = __expf(vals[i] - mx); sum += vals[i]; }
    red[tid] = sum; __syncthreads();
    for (int s = 128; s > 0; s >>= 1) { if (tid < s) red[tid] += red[tid + s]; __syncthreads(); }
    const float inv = 1.0f / red[0];
    #pragma unroll
    for (int i = 0; i < 8; i++) row[tid + i * 256] = vals[i] * inv;
}

// ---------------------------------------------------------------------------
extern "C" void kernel_launch(void* const* d_in, const int* in_sizes, int n_in,
                              void* d_out, int out_size)
{
    const float* query = (const float*)d_in[0];
    const float* feat  = (const float*)d_in[1];
    const float* Wi    = (const float*)d_in[2];
    const float* bi    = (const float*)d_in[3];
    const float* Wo    = (const float*)d_in[4];
    const float* bo    = (const float*)d_in[5];

    float* out = (float*)d_out;
    float* attn_out = out;
    float* aw = out + (size_t)T_DIM * B_DIM * D_DIM;

    float *kv, *ctx;
    __nv_bfloat16 *feat_e, *wi_e, *wo_e, *q_e, *k_e, *p_e, *vt_e, *ctx_e;
    cudaGetSymbolAddress((void**)&kv, g_kv);
    cudaGetSymbolAddress((void**)&ctx, g_ctx);
    cudaGetSymbolAddress((void**)&feat_e, g_feat_ext);
    cudaGetSymbolAddress((void**)&wi_e, g_wi_ext);
    cudaGetSymbolAddress((void**)&wo_e, g_wo_ext);
    cudaGetSymbolAddress((void**)&q_e, g_q_ext);
    cudaGetSymbolAddress((void**)&k_e, g_k_ext);
    cudaGetSymbolAddress((void**)&p_e, g_p_ext);
    cudaGetSymbolAddress((void**)&vt_e, g_vt_ext);
    cudaGetSymbolAddress((void**)&ctx_e, g_ctx_ext);

    const float scale = 0.03125f;
    const long TT = (long)T_DIM * T_DIM;

    split_conv<<<dim3((T_DIM * B_DIM * D_DIM) / 256, 1, 1), 256>>>(feat, 0, D_DIM, feat_e, T_DIM * B_DIM, D_DIM, 1.f, 1);
    split_conv<<<dim3((2 * D_DIM * D_DIM) / 256, 1, 1), 256>>>(Wi, 0, D_DIM, wi_e, 2 * D_DIM, D_DIM, 1.f, 0);
    split_conv<<<dim3((D_DIM * D_DIM) / 256, 1, 1), 256>>>(Wo, 0, D_DIM, wo_e, D_DIM, D_DIM, 1.f, 0);
    split_conv<<<dim3((T_DIM * D_DIM) / 256, 1, B_DIM), 256>>>(query, D_DIM, (long)B_DIM * D_DIM, q_e, T_DIM, D_DIM, scale, 1);

    // 1) KV projection (M=8192, N=2048, K'=3072)
    gemm_mma<<<dim3(2 * D_DIM / BN, T_DIM * B_DIM / BM, 1), 256>>>(
        feat_e, 0, KEXT1, wi_e, 0, KEXT1, kv, 0, 2 * D_DIM, bi, KEXT1);

    split_conv<<<dim3((T_DIM * D_DIM) / 256, 1, B_DIM), 256>>>(kv, 2 * D_DIM, (long)B_DIM * 2 * D_DIM, k_e, T_DIM, D_DIM, 1.f, 0);
    vt_conv<<<dim3(T_DIM / 32, D_DIM / 32, B_DIM), 256>>>(kv, vt_e);

    // 2) scores (M=2048, N=2048, K'=3072) batched over B
    gemm_mma<<<dim3(T_DIM / BN, T_DIM / BM, B_DIM), 256>>>(
        q_e, (long)T_DIM * KEXT1, KEXT1, k_e, (long)T_DIM * KEXT1, KEXT1,
        aw, TT, T_DIM, nullptr, KEXT1);

    // 3) softmax
    softmax_kernel<<<B_DIM * T_DIM, 256>>>(aw);

    split_conv<<<dim3((int)(TT / 256), 1, B_DIM), 256>>>(aw, TT, T_DIM, p_e, T_DIM, T_DIM, 1.f, 1);

    // 4) context (M=2048, N=1024, K'=6144) batched
    gemm_mma<<<dim3(D_DIM / BN, T_DIM / BM, B_DIM), 256>>>(
        p_e, (long)T_DIM * KEXT2, KEXT2, vt_e, (long)D_DIM * KEXT2, KEXT2,
        ctx, D_DIM, B_DIM * D_DIM, nullptr, KEXT2);

    split_conv<<<dim3((T_DIM * B_DIM * D_DIM) / 256, 1, 1), 256>>>(ctx, 0, D_DIM, ctx_e, T_DIM * B_DIM, D_DIM, 1.f, 1);

    // 5) out projection (M=8192, N=1024, K'=3072)
    gemm_mma<<<dim3(D_DIM / BN, T_DIM * B_DIM / BM, 1), 256>>>(
        ctx_e, 0, KEXT1, wo_e, 0, KEXT1, attn_out, 0, D_DIM, bo, KEXT1);
}